// round 7
// baseline (speedup 1.0000x reference)
#include <cuda_runtime.h>
#include <cuda_fp16.h>

#define N_NODES 100000
#define N_EDGES 1600000
#define DIM 128
#define NB_SCAN 391   // ceil(100000/256)

// Scratch (allocation-free rule: __device__ globals)
__device__ __half g_xw[(size_t)N_NODES * DIM];  // 25.6 MB, fp16
__device__ float g_dis[N_NODES];
__device__ int   g_deg[N_NODES];
__device__ int   g_off[N_NODES];     // exclusive prefix of deg
__device__ int   g_cur[N_NODES];     // placement cursors
__device__ int   g_erow[N_EDGES];    // edge source, sorted by target
__device__ float g_ew[N_EDGES];      // edge weight dis[r]*dis[c], same order
__device__ int   g_bsum[NB_SCAN];
__device__ int   g_boff[NB_SCAN];
__device__ int   g_orflag;           // OR of sampled odd int32 words; 0 => int64

// ---------------- zero counters + flag ----------------
__global__ void k_init() {
    int i = blockIdx.x * blockDim.x + threadIdx.x;
    if (i < N_NODES) g_deg[i] = 0;
    if (i == 0) g_orflag = 0;
}

// ---------------- dtype detect (sampled: 8192 odd words, 1 block) ----------------
__global__ void k_detect(const int* __restrict__ ei32) {
    int t = threadIdx.x;
    int acc = 0;
#pragma unroll
    for (int s = 0; s < 32; s++) {
        int j = t + s * 256;                  // 0..8191
        long long idx = (long long)j * 195;   // spread over ~1.6M entries
        acc |= ei32[2 * idx + 1];
    }
    if (acc != 0) atomicOr(&g_orflag, 1);
}

// ---------------- degree histogram (vectorized int64 path) ----------------
__global__ void k_hist(const int* __restrict__ ei32) {
    int t = blockIdx.x * blockDim.x + threadIdx.x;   // 0 .. N_EDGES/2-1
    if (t >= N_EDGES / 2) return;
    if (g_orflag == 0) {
        // int64 layout: col half starts at word 2*N_EDGES; int4 = 2 entries
        const int4* p = (const int4*)(ei32 + 2 * N_EDGES);
        int4 v = __ldg(&p[t]);
        atomicAdd(&g_deg[v.x], 1);
        atomicAdd(&g_deg[v.z], 1);
    } else {
        // int32 layout: col half starts at word N_EDGES; int2 = 2 entries
        const int2* p = (const int2*)(ei32 + N_EDGES);
        int2 v = __ldg(&p[t]);
        atomicAdd(&g_deg[v.x], 1);
        atomicAdd(&g_deg[v.y], 1);
    }
}

// ---------------- scan1 (fused: also computes g_dis) ----------------
__global__ __launch_bounds__(256) void k_scan1() {
    __shared__ int s[256];
    int t = threadIdx.x;
    int i = blockIdx.x * 256 + t;
    int v = (i < N_NODES) ? g_deg[i] : 0;
    if (i < N_NODES) g_dis[i] = rsqrtf((float)(v + 1)); // +1 self loop
    s[t] = v; __syncthreads();
#pragma unroll
    for (int off = 1; off < 256; off <<= 1) {
        int tmp = (t >= off) ? s[t - off] : 0;
        __syncthreads();
        s[t] += tmp;
        __syncthreads();
    }
    if (i < N_NODES) g_off[i] = s[t] - v;
    if (t == 255) g_bsum[blockIdx.x] = s[255];
}

__global__ __launch_bounds__(512) void k_scan2() {
    __shared__ int s[512];
    int t = threadIdx.x;
    int v = (t < NB_SCAN) ? g_bsum[t] : 0;
    s[t] = v; __syncthreads();
#pragma unroll
    for (int off = 1; off < 512; off <<= 1) {
        int tmp = (t >= off) ? s[t - off] : 0;
        __syncthreads();
        s[t] += tmp;
        __syncthreads();
    }
    if (t < NB_SCAN) g_boff[t] = s[t] - v;
}

__global__ __launch_bounds__(256) void k_scan3() {
    int i = blockIdx.x * 256 + threadIdx.x;
    if (i < N_NODES) {
        int o = g_off[i] + g_boff[blockIdx.x];
        g_off[i] = o;
        g_cur[i] = o;
    }
}

// ---------------- place edges into CSR buckets; precompute edge weights ----------------
__global__ void k_place(const int* __restrict__ ei32) {
    int e = blockIdx.x * blockDim.x + threadIdx.x;
    if (e >= N_EDGES) return;
    int r, c;
    if (g_orflag == 0) {  // int64 layout: low words
        r = ei32[2 * e];
        c = ei32[2 * (N_EDGES + e)];
    } else {              // int32 layout
        r = ei32[e];
        c = ei32[N_EDGES + e];
    }
    int pos = atomicAdd(&g_cur[c], 1);
    g_erow[pos] = r;
    g_ew[pos] = __ldg(&g_dis[r]) * __ldg(&g_dis[c]);
}

// ---------------- tf32 tensor-core GEMM: g_xw = fp16(x @ W) ----------------
__global__ __launch_bounds__(256) void k_gemm(const float* __restrict__ x,
                                              const float* __restrict__ W) {
    __shared__ unsigned As[128][36];
    __shared__ unsigned Bs[32][136];
    const int m0   = blockIdx.x * 128;
    const int tid  = threadIdx.x;
    const int warp = tid >> 5;
    const int lane = tid & 31;
    const int wm   = warp >> 1;   // 0..3
    const int wn   = warp & 1;    // 0..1
    const int qr   = lane >> 2;   // 0..7
    const int qc   = lane & 3;    // 0..3

    float acc[2][8][4];
#pragma unroll
    for (int mi = 0; mi < 2; mi++)
#pragma unroll
        for (int ni = 0; ni < 8; ni++)
#pragma unroll
            for (int j = 0; j < 4; j++) acc[mi][ni][j] = 0.f;

#pragma unroll 1
    for (int kt = 0; kt < 4; kt++) {
#pragma unroll
        for (int i = 0; i < 16; i++) {
            int idx = tid + i * 256;
            int r = idx >> 5, c = idx & 31;
            int gr = m0 + r;
            float v = (gr < N_NODES) ? __ldg(&x[(size_t)gr * DIM + kt * 32 + c]) : 0.f;
            unsigned u;
            asm("cvt.rna.tf32.f32 %0, %1;" : "=r"(u) : "f"(v));
            As[r][c] = u;
        }
#pragma unroll
        for (int i = 0; i < 16; i++) {
            int idx = tid + i * 256;
            int r = idx >> 7, c = idx & 127;
            float v = __ldg(&W[(kt * 32 + r) * DIM + c]);
            unsigned u;
            asm("cvt.rna.tf32.f32 %0, %1;" : "=r"(u) : "f"(v));
            Bs[r][c] = u;
        }
        __syncthreads();

#pragma unroll
        for (int ks = 0; ks < 4; ks++) {
            const int k0 = ks * 8;
            unsigned a[2][4], bf[8][2];
#pragma unroll
            for (int mi = 0; mi < 2; mi++) {
                int rb = wm * 32 + mi * 16;
                a[mi][0] = As[rb + qr][k0 + qc];
                a[mi][1] = As[rb + qr + 8][k0 + qc];
                a[mi][2] = As[rb + qr][k0 + qc + 4];
                a[mi][3] = As[rb + qr + 8][k0 + qc + 4];
            }
#pragma unroll
            for (int ni = 0; ni < 8; ni++) {
                int cb = wn * 64 + ni * 8;
                bf[ni][0] = Bs[k0 + qc][cb + qr];
                bf[ni][1] = Bs[k0 + qc + 4][cb + qr];
            }
#pragma unroll
            for (int mi = 0; mi < 2; mi++)
#pragma unroll
                for (int ni = 0; ni < 8; ni++) {
                    asm volatile(
                        "mma.sync.aligned.m16n8k8.row.col.f32.tf32.tf32.f32 "
                        "{%0,%1,%2,%3}, {%4,%5,%6,%7}, {%8,%9}, {%0,%1,%2,%3};"
                        : "+f"(acc[mi][ni][0]), "+f"(acc[mi][ni][1]),
                          "+f"(acc[mi][ni][2]), "+f"(acc[mi][ni][3])
                        : "r"(a[mi][0]), "r"(a[mi][1]), "r"(a[mi][2]), "r"(a[mi][3]),
                          "r"(bf[ni][0]), "r"(bf[ni][1]));
                }
        }
        __syncthreads();
    }

#pragma unroll
    for (int mi = 0; mi < 2; mi++) {
        int r0 = m0 + wm * 32 + mi * 16 + qr;
        int r1 = r0 + 8;
#pragma unroll
        for (int ni = 0; ni < 8; ni++) {
            int cb = wn * 64 + ni * 8 + qc * 2;
            if (r0 < N_NODES)
                *(__half2*)&g_xw[(size_t)r0 * DIM + cb] =
                    __floats2half2_rn(acc[mi][ni][0], acc[mi][ni][1]);
            if (r1 < N_NODES)
                *(__half2*)&g_xw[(size_t)r1 * DIM + cb] =
                    __floats2half2_rn(acc[mi][ni][2], acc[mi][ni][3]);
        }
    }
}

// ---------------- CSR gather: warp/node, vectorized idx/weight loads ----------------
__device__ __forceinline__ void gacc(float4& acc, const uint2& u, float w) {
    float2 a0 = __half22float2(*(const __half2*)&u.x);
    float2 a1 = __half22float2(*(const __half2*)&u.y);
    acc.x += a0.x * w; acc.y += a0.y * w;
    acc.z += a1.x * w; acc.w += a1.y * w;
}

__global__ __launch_bounds__(256) void k_gather(const float* __restrict__ b,
                                                float* __restrict__ out) {
    int n    = (blockIdx.x * blockDim.x + threadIdx.x) >> 5;
    int lane = threadIdx.x & 31;
    if (n >= N_NODES) return;

    const uint2* xw2 = (const uint2*)g_xw;  // 8 B per lane = 4 fp16 features
    float dn = g_dis[n];

    uint2 us = __ldg(&xw2[(size_t)n * 32 + lane]);
    float sn = dn * dn;
    float4 acc = make_float4(0.f, 0.f, 0.f, 0.f);
    gacc(acc, us, sn);

    int beg = g_off[n];
    int end = (n + 1 < N_NODES) ? g_off[n + 1] : N_EDGES;

    int e = beg;
    // scalar until 4-aligned
    for (; e < end && (e & 3); e++) {
        int r0 = __ldg(&g_erow[e]);
        float w0 = __ldg(&g_ew[e]);
        uint2 u0 = __ldg(&xw2[(size_t)r0 * 32 + lane]);
        gacc(acc, u0, w0);
    }
    // 8-wide: 2x int4 + 2x float4 + 8 independent row loads
    for (; e + 7 < end; e += 8) {
        int4   i0 = __ldg((const int4*)&g_erow[e]);
        int4   i1 = __ldg((const int4*)&g_erow[e + 4]);
        float4 w0 = __ldg((const float4*)&g_ew[e]);
        float4 w1 = __ldg((const float4*)&g_ew[e + 4]);
        uint2 u0 = __ldg(&xw2[(size_t)i0.x * 32 + lane]);
        uint2 u1 = __ldg(&xw2[(size_t)i0.y * 32 + lane]);
        uint2 u2 = __ldg(&xw2[(size_t)i0.z * 32 + lane]);
        uint2 u3 = __ldg(&xw2[(size_t)i0.w * 32 + lane]);
        uint2 u4 = __ldg(&xw2[(size_t)i1.x * 32 + lane]);
        uint2 u5 = __ldg(&xw2[(size_t)i1.y * 32 + lane]);
        uint2 u6 = __ldg(&xw2[(size_t)i1.z * 32 + lane]);
        uint2 u7 = __ldg(&xw2[(size_t)i1.w * 32 + lane]);
        gacc(acc, u0, w0.x); gacc(acc, u1, w0.y);
        gacc(acc, u2, w0.z); gacc(acc, u3, w0.w);
        gacc(acc, u4, w1.x); gacc(acc, u5, w1.y);
        gacc(acc, u6, w1.z); gacc(acc, u7, w1.w);
    }
    // 4-wide
    for (; e + 3 < end; e += 4) {
        int4   i0 = __ldg((const int4*)&g_erow[e]);
        float4 w0 = __ldg((const float4*)&g_ew[e]);
        uint2 u0 = __ldg(&xw2[(size_t)i0.x * 32 + lane]);
        uint2 u1 = __ldg(&xw2[(size_t)i0.y * 32 + lane]);
        uint2 u2 = __ldg(&xw2[(size_t)i0.z * 32 + lane]);
        uint2 u3 = __ldg(&xw2[(size_t)i0.w * 32 + lane]);
        gacc(acc, u0, w0.x); gacc(acc, u1, w0.y);
        gacc(acc, u2, w0.z); gacc(acc, u3, w0.w);
    }
    // tail
    for (; e < end; e++) {
        int r0 = __ldg(&g_erow[e]);
        float w0 = __ldg(&g_ew[e]);
        uint2 u0 = __ldg(&xw2[(size_t)r0 * 32 + lane]);
        gacc(acc, u0, w0);
    }

    float4 bb = ((const float4*)b)[lane];
    acc.x = fmaxf(acc.x + bb.x, 0.f);
    acc.y = fmaxf(acc.y + bb.y, 0.f);
    acc.z = fmaxf(acc.z + bb.z, 0.f);
    acc.w = fmaxf(acc.w + bb.w, 0.f);
    ((float4*)out)[(size_t)n * 32 + lane] = acc;
}

extern "C" void kernel_launch(void* const* d_in, const int* in_sizes, int n_in,
                              void* d_out, int out_size) {
    // Identify inputs by element count:
    //   x: 12,800,000   edge_index: 3,200,000   W: 16,384   b: 128
    const float* x  = nullptr;
    const void*  ei = nullptr;
    const float* W  = nullptr;
    const float* b  = nullptr;
    for (int i = 0; i < n_in; i++) {
        switch (in_sizes[i]) {
            case 12800000: x  = (const float*)d_in[i]; break;
            case 3200000:  ei = d_in[i];               break;
            case 16384:    W  = (const float*)d_in[i]; break;
            case 128:      b  = (const float*)d_in[i]; break;
            default: break;
        }
    }
    float* out = (float*)d_out;
    const int* ei32 = (const int*)ei;

    // Fork: GEMM (depends only on x, W) runs on a side stream in parallel
    // with the edge-preprocessing chain; join before gather.
    cudaStream_t s2;
    cudaStreamCreateWithFlags(&s2, cudaStreamNonBlocking);
    cudaEvent_t ev_fork, ev_join;
    cudaEventCreateWithFlags(&ev_fork, cudaEventDisableTiming);
    cudaEventCreateWithFlags(&ev_join, cudaEventDisableTiming);

    cudaEventRecord(ev_fork, 0);
    cudaStreamWaitEvent(s2, ev_fork, 0);
    k_gemm<<<(N_NODES + 127) / 128, 256, 0, s2>>>(x, W);
    cudaEventRecord(ev_join, s2);

    // main-stream preprocessing chain
    k_init<<<(N_NODES + 255) / 256, 256>>>();
    k_detect<<<1, 256>>>(ei32);
    k_hist<<<(N_EDGES / 2 + 255) / 256, 256>>>(ei32);
    k_scan1<<<NB_SCAN, 256>>>();
    k_scan2<<<1, 512>>>();
    k_scan3<<<NB_SCAN, 256>>>();
    k_place<<<(N_EDGES + 255) / 256, 256>>>(ei32);

    cudaStreamWaitEvent(0, ev_join, 0);
    {
        long long total_threads = (long long)N_NODES * 32;
        int blocks = (int)((total_threads + 255) / 256);
        k_gather<<<blocks, 256>>>(b, out);
    }
}

// round 8
// speedup vs baseline: 1.0353x; 1.0353x over previous
#include <cuda_runtime.h>
#include <cuda_fp16.h>

#define N_NODES 100000
#define N_EDGES 1600000
#define DIM 128
#define NB_SCAN 391   // ceil(100000/256)

// Scratch (allocation-free rule: __device__ globals)
__device__ __half g_xw[(size_t)N_NODES * DIM];  // 25.6 MB, fp16
__device__ float g_dis[N_NODES];
__device__ int   g_deg[N_NODES];
__device__ int   g_off[N_NODES];     // exclusive prefix of deg
__device__ int   g_cur[N_NODES];     // placement cursors
__device__ int   g_erow[N_EDGES];    // edge source, sorted by target
__device__ int   g_bsum[NB_SCAN];
__device__ int   g_boff[NB_SCAN];
__device__ int   g_orflag;           // OR of sampled odd int32 words; 0 => int64

// ---------------- fused: zero deg counters + dtype detect ----------------
__global__ void k_init_detect(const int* __restrict__ ei32) {
    int i = blockIdx.x * blockDim.x + threadIdx.x;
    if (i < N_NODES) g_deg[i] = 0;
    if (blockIdx.x == 0) {
        if (threadIdx.x == 0) g_orflag = 0;
        __syncthreads();
        int t = threadIdx.x;
        int acc = 0;
#pragma unroll
        for (int s = 0; s < 32; s++) {
            int j = t + s * 256;                  // 0..8191
            long long idx = (long long)j * 195;   // spread over ~1.6M entries
            acc |= ei32[2 * idx + 1];
        }
        if (acc != 0) atomicOr(&g_orflag, 1);
    }
}

// ---------------- degree histogram (vectorized) ----------------
__global__ void k_hist(const int* __restrict__ ei32) {
    int t = blockIdx.x * blockDim.x + threadIdx.x;   // 0 .. N_EDGES/2-1
    if (t >= N_EDGES / 2) return;
    if (g_orflag == 0) {
        // int64 layout: col half starts at word 2*N_EDGES; int4 = 2 entries
        const int4* p = (const int4*)(ei32 + 2 * N_EDGES);
        int4 v = __ldg(&p[t]);
        atomicAdd(&g_deg[v.x], 1);
        atomicAdd(&g_deg[v.z], 1);
    } else {
        // int32 layout: col half starts at word N_EDGES; int2 = 2 entries
        const int2* p = (const int2*)(ei32 + N_EDGES);
        int2 v = __ldg(&p[t]);
        atomicAdd(&g_deg[v.x], 1);
        atomicAdd(&g_deg[v.y], 1);
    }
}

// ---------------- scan1 (fused: also computes g_dis) ----------------
__global__ __launch_bounds__(256) void k_scan1() {
    __shared__ int s[256];
    int t = threadIdx.x;
    int i = blockIdx.x * 256 + t;
    int v = (i < N_NODES) ? g_deg[i] : 0;
    if (i < N_NODES) g_dis[i] = rsqrtf((float)(v + 1)); // +1 self loop
    s[t] = v; __syncthreads();
#pragma unroll
    for (int off = 1; off < 256; off <<= 1) {
        int tmp = (t >= off) ? s[t - off] : 0;
        __syncthreads();
        s[t] += tmp;
        __syncthreads();
    }
    if (i < N_NODES) g_off[i] = s[t] - v;
    if (t == 255) g_bsum[blockIdx.x] = s[255];
}

__global__ __launch_bounds__(512) void k_scan2() {
    __shared__ int s[512];
    int t = threadIdx.x;
    int v = (t < NB_SCAN) ? g_bsum[t] : 0;
    s[t] = v; __syncthreads();
#pragma unroll
    for (int off = 1; off < 512; off <<= 1) {
        int tmp = (t >= off) ? s[t - off] : 0;
        __syncthreads();
        s[t] += tmp;
        __syncthreads();
    }
    if (t < NB_SCAN) g_boff[t] = s[t] - v;
}

__global__ __launch_bounds__(256) void k_scan3() {
    int i = blockIdx.x * 256 + threadIdx.x;
    if (i < N_NODES) {
        int o = g_off[i] + g_boff[blockIdx.x];
        g_off[i] = o;
        g_cur[i] = o;
    }
}

// ---------------- place edges into CSR buckets (2 edges/thread, vectorized) ----------------
__global__ void k_place(const int* __restrict__ ei32) {
    int t = blockIdx.x * blockDim.x + threadIdx.x;   // 0 .. N_EDGES/2-1
    if (t >= N_EDGES / 2) return;
    int r0, r1, c0, c1;
    if (g_orflag == 0) {
        // int64 layout: rows at words [0, 4*t..], cols at [2*N_EDGES + 4*t..]
        int4 vr = __ldg(&((const int4*)ei32)[t]);
        int4 vc = __ldg(&((const int4*)(ei32 + 2 * N_EDGES))[t]);
        r0 = vr.x; r1 = vr.z;
        c0 = vc.x; c1 = vc.z;
    } else {
        int2 vr = __ldg(&((const int2*)ei32)[t]);
        int2 vc = __ldg(&((const int2*)(ei32 + N_EDGES))[t]);
        r0 = vr.x; r1 = vr.y;
        c0 = vc.x; c1 = vc.y;
    }
    int p0 = atomicAdd(&g_cur[c0], 1);
    int p1 = atomicAdd(&g_cur[c1], 1);
    g_erow[p0] = r0;
    g_erow[p1] = r1;
}

// ---------------- tf32 tensor-core GEMM: g_xw = fp16(x @ W) ----------------
__global__ __launch_bounds__(256) void k_gemm(const float* __restrict__ x,
                                              const float* __restrict__ W) {
    __shared__ unsigned As[128][36];
    __shared__ unsigned Bs[32][136];
    const int m0   = blockIdx.x * 128;
    const int tid  = threadIdx.x;
    const int warp = tid >> 5;
    const int lane = tid & 31;
    const int wm   = warp >> 1;   // 0..3
    const int wn   = warp & 1;    // 0..1
    const int qr   = lane >> 2;   // 0..7
    const int qc   = lane & 3;    // 0..3

    float acc[2][8][4];
#pragma unroll
    for (int mi = 0; mi < 2; mi++)
#pragma unroll
        for (int ni = 0; ni < 8; ni++)
#pragma unroll
            for (int j = 0; j < 4; j++) acc[mi][ni][j] = 0.f;

#pragma unroll 1
    for (int kt = 0; kt < 4; kt++) {
#pragma unroll
        for (int i = 0; i < 16; i++) {
            int idx = tid + i * 256;
            int r = idx >> 5, c = idx & 31;
            int gr = m0 + r;
            float v = (gr < N_NODES) ? __ldg(&x[(size_t)gr * DIM + kt * 32 + c]) : 0.f;
            unsigned u;
            asm("cvt.rna.tf32.f32 %0, %1;" : "=r"(u) : "f"(v));
            As[r][c] = u;
        }
#pragma unroll
        for (int i = 0; i < 16; i++) {
            int idx = tid + i * 256;
            int r = idx >> 7, c = idx & 127;
            float v = __ldg(&W[(kt * 32 + r) * DIM + c]);
            unsigned u;
            asm("cvt.rna.tf32.f32 %0, %1;" : "=r"(u) : "f"(v));
            Bs[r][c] = u;
        }
        __syncthreads();

#pragma unroll
        for (int ks = 0; ks < 4; ks++) {
            const int k0 = ks * 8;
            unsigned a[2][4], bf[8][2];
#pragma unroll
            for (int mi = 0; mi < 2; mi++) {
                int rb = wm * 32 + mi * 16;
                a[mi][0] = As[rb + qr][k0 + qc];
                a[mi][1] = As[rb + qr + 8][k0 + qc];
                a[mi][2] = As[rb + qr][k0 + qc + 4];
                a[mi][3] = As[rb + qr + 8][k0 + qc + 4];
            }
#pragma unroll
            for (int ni = 0; ni < 8; ni++) {
                int cb = wn * 64 + ni * 8;
                bf[ni][0] = Bs[k0 + qc][cb + qr];
                bf[ni][1] = Bs[k0 + qc + 4][cb + qr];
            }
#pragma unroll
            for (int mi = 0; mi < 2; mi++)
#pragma unroll
                for (int ni = 0; ni < 8; ni++) {
                    asm volatile(
                        "mma.sync.aligned.m16n8k8.row.col.f32.tf32.tf32.f32 "
                        "{%0,%1,%2,%3}, {%4,%5,%6,%7}, {%8,%9}, {%0,%1,%2,%3};"
                        : "+f"(acc[mi][ni][0]), "+f"(acc[mi][ni][1]),
                          "+f"(acc[mi][ni][2]), "+f"(acc[mi][ni][3])
                        : "r"(a[mi][0]), "r"(a[mi][1]), "r"(a[mi][2]), "r"(a[mi][3]),
                          "r"(bf[ni][0]), "r"(bf[ni][1]));
                }
        }
        __syncthreads();
    }

#pragma unroll
    for (int mi = 0; mi < 2; mi++) {
        int r0 = m0 + wm * 32 + mi * 16 + qr;
        int r1 = r0 + 8;
#pragma unroll
        for (int ni = 0; ni < 8; ni++) {
            int cb = wn * 64 + ni * 8 + qc * 2;
            if (r0 < N_NODES)
                *(__half2*)&g_xw[(size_t)r0 * DIM + cb] =
                    __floats2half2_rn(acc[mi][ni][0], acc[mi][ni][1]);
            if (r1 < N_NODES)
                *(__half2*)&g_xw[(size_t)r1 * DIM + cb] =
                    __floats2half2_rn(acc[mi][ni][2], acc[mi][ni][3]);
        }
    }
}

// ---------------- CSR gather: warp/node, 4-edge unroll for MLP (R6-proven) ----------------
__global__ __launch_bounds__(256) void k_gather(const float* __restrict__ b,
                                                float* __restrict__ out) {
    int n    = (blockIdx.x * blockDim.x + threadIdx.x) >> 5;
    int lane = threadIdx.x & 31;
    if (n >= N_NODES) return;

    const uint2* xw2 = (const uint2*)g_xw;  // 8 B per lane = 4 fp16 features
    float dn = g_dis[n];

    uint2 us = __ldg(&xw2[(size_t)n * 32 + lane]);
    float2 s0 = __half22float2(*(__half2*)&us.x);
    float2 s1 = __half22float2(*(__half2*)&us.y);
    float sn = dn * dn;
    float4 acc = make_float4(s0.x * sn, s0.y * sn, s1.x * sn, s1.y * sn);

    int beg = g_off[n];
    int end = (n + 1 < N_NODES) ? g_off[n + 1] : N_EDGES;

    int e = beg;
    for (; e + 3 < end; e += 4) {
        int r0 = __ldg(&g_erow[e]);
        int r1 = __ldg(&g_erow[e + 1]);
        int r2 = __ldg(&g_erow[e + 2]);
        int r3 = __ldg(&g_erow[e + 3]);
        float w0 = __ldg(&g_dis[r0]) * dn;
        float w1 = __ldg(&g_dis[r1]) * dn;
        float w2 = __ldg(&g_dis[r2]) * dn;
        float w3 = __ldg(&g_dis[r3]) * dn;
        uint2 u0 = __ldg(&xw2[(size_t)r0 * 32 + lane]);
        uint2 u1 = __ldg(&xw2[(size_t)r1 * 32 + lane]);
        uint2 u2 = __ldg(&xw2[(size_t)r2 * 32 + lane]);
        uint2 u3 = __ldg(&xw2[(size_t)r3 * 32 + lane]);
        float2 a0 = __half22float2(*(__half2*)&u0.x);
        float2 a1 = __half22float2(*(__half2*)&u0.y);
        float2 b0 = __half22float2(*(__half2*)&u1.x);
        float2 b1 = __half22float2(*(__half2*)&u1.y);
        float2 c0 = __half22float2(*(__half2*)&u2.x);
        float2 c1 = __half22float2(*(__half2*)&u2.y);
        float2 d0 = __half22float2(*(__half2*)&u3.x);
        float2 d1 = __half22float2(*(__half2*)&u3.y);
        acc.x += a0.x * w0 + b0.x * w1 + c0.x * w2 + d0.x * w3;
        acc.y += a0.y * w0 + b0.y * w1 + c0.y * w2 + d0.y * w3;
        acc.z += a1.x * w0 + b1.x * w1 + c1.x * w2 + d1.x * w3;
        acc.w += a1.y * w0 + b1.y * w1 + c1.y * w2 + d1.y * w3;
    }
    for (; e < end; e++) {
        int r0 = __ldg(&g_erow[e]);
        float w0 = __ldg(&g_dis[r0]) * dn;
        uint2 u0 = __ldg(&xw2[(size_t)r0 * 32 + lane]);
        float2 a0 = __half22float2(*(__half2*)&u0.x);
        float2 a1 = __half22float2(*(__half2*)&u0.y);
        acc.x += a0.x * w0; acc.y += a0.y * w0;
        acc.z += a1.x * w0; acc.w += a1.y * w0;
    }

    float4 bb = ((const float4*)b)[lane];
    acc.x = fmaxf(acc.x + bb.x, 0.f);
    acc.y = fmaxf(acc.y + bb.y, 0.f);
    acc.z = fmaxf(acc.z + bb.z, 0.f);
    acc.w = fmaxf(acc.w + bb.w, 0.f);
    ((float4*)out)[(size_t)n * 32 + lane] = acc;
}

extern "C" void kernel_launch(void* const* d_in, const int* in_sizes, int n_in,
                              void* d_out, int out_size) {
    // Identify inputs by element count:
    //   x: 12,800,000   edge_index: 3,200,000   W: 16,384   b: 128
    const float* x  = nullptr;
    const void*  ei = nullptr;
    const float* W  = nullptr;
    const float* b  = nullptr;
    for (int i = 0; i < n_in; i++) {
        switch (in_sizes[i]) {
            case 12800000: x  = (const float*)d_in[i]; break;
            case 3200000:  ei = d_in[i];               break;
            case 16384:    W  = (const float*)d_in[i]; break;
            case 128:      b  = (const float*)d_in[i]; break;
            default: break;
        }
    }
    float* out = (float*)d_out;
    const int* ei32 = (const int*)ei;

    // Fork: GEMM (depends only on x, W) runs on a side stream in parallel
    // with the edge-preprocessing chain; join before gather.
    cudaStream_t s2;
    cudaStreamCreateWithFlags(&s2, cudaStreamNonBlocking);
    cudaEvent_t ev_fork, ev_join;
    cudaEventCreateWithFlags(&ev_fork, cudaEventDisableTiming);
    cudaEventCreateWithFlags(&ev_join, cudaEventDisableTiming);

    cudaEventRecord(ev_fork, 0);
    cudaStreamWaitEvent(s2, ev_fork, 0);
    k_gemm<<<(N_NODES + 127) / 128, 256, 0, s2>>>(x, W);
    cudaEventRecord(ev_join, s2);

    // main-stream preprocessing chain
    k_init_detect<<<(N_NODES + 255) / 256, 256>>>(ei32);
    k_hist<<<(N_EDGES / 2 + 255) / 256, 256>>>(ei32);
    k_scan1<<<NB_SCAN, 256>>>();
    k_scan2<<<1, 512>>>();
    k_scan3<<<NB_SCAN, 256>>>();
    k_place<<<(N_EDGES / 2 + 255) / 256, 256>>>(ei32);

    cudaStreamWaitEvent(0, ev_join, 0);
    {
        long long total_threads = (long long)N_NODES * 32;
        int blocks = (int)((total_threads + 255) / 256);
        k_gather<<<blocks, 256>>>(b, out);
    }
}

// round 9
// speedup vs baseline: 1.0958x; 1.0584x over previous
#include <cuda_runtime.h>
#include <cuda_fp16.h>

#define N_NODES 100000
#define N_EDGES 1600000
#define DIM 128
#define NB_SCAN 391   // ceil(100000/256)

// Scratch (allocation-free rule: __device__ globals)
__device__ __half g_xw[(size_t)N_NODES * DIM];  // 25.6 MB, fp16
__device__ float g_dis[N_NODES];
__device__ int   g_deg[N_NODES];
__device__ int   g_off[N_NODES];     // exclusive prefix of deg
__device__ int   g_cur[N_NODES];     // placement cursors
__device__ int   g_erow[N_EDGES];    // edge source, sorted by target
__device__ int   g_bsum[NB_SCAN];
__device__ int   g_orflag;           // OR of sampled odd int32 words; 0 => int64

// ---------------- fused: zero deg counters + dtype detect ----------------
__global__ void k_init_detect(const int* __restrict__ ei32) {
    int i = blockIdx.x * blockDim.x + threadIdx.x;
    if (i < N_NODES) g_deg[i] = 0;
    if (blockIdx.x == 0) {
        if (threadIdx.x == 0) g_orflag = 0;
        __syncthreads();
        int t = threadIdx.x;
        int acc = 0;
#pragma unroll
        for (int s = 0; s < 32; s++) {
            int j = t + s * 256;                  // 0..8191
            long long idx = (long long)j * 195;   // spread over ~1.6M entries
            acc |= ei32[2 * idx + 1];
        }
        if (acc != 0) atomicOr(&g_orflag, 1);
    }
}

// ---------------- degree histogram (vectorized) ----------------
__global__ void k_hist(const int* __restrict__ ei32) {
    int t = blockIdx.x * blockDim.x + threadIdx.x;   // 0 .. N_EDGES/2-1
    if (t >= N_EDGES / 2) return;
    if (g_orflag == 0) {
        const int4* p = (const int4*)(ei32 + 2 * N_EDGES);
        int4 v = __ldg(&p[t]);
        atomicAdd(&g_deg[v.x], 1);
        atomicAdd(&g_deg[v.z], 1);
    } else {
        const int2* p = (const int2*)(ei32 + N_EDGES);
        int2 v = __ldg(&p[t]);
        atomicAdd(&g_deg[v.x], 1);
        atomicAdd(&g_deg[v.y], 1);
    }
}

// ---------------- scan1 (fused: also computes g_dis) ----------------
__global__ __launch_bounds__(256) void k_scan1() {
    __shared__ int s[256];
    int t = threadIdx.x;
    int i = blockIdx.x * 256 + t;
    int v = (i < N_NODES) ? g_deg[i] : 0;
    if (i < N_NODES) g_dis[i] = rsqrtf((float)(v + 1)); // +1 self loop
    s[t] = v; __syncthreads();
#pragma unroll
    for (int off = 1; off < 256; off <<= 1) {
        int tmp = (t >= off) ? s[t - off] : 0;
        __syncthreads();
        s[t] += tmp;
        __syncthreads();
    }
    if (i < N_NODES) g_off[i] = s[t] - v;      // block-local exclusive
    if (t == 255) g_bsum[blockIdx.x] = s[255];
}

// ---------------- scan2+3 fused: each block reduces prior block sums itself ----------------
__global__ __launch_bounds__(256) void k_scan23() {
    __shared__ int red[256];
    int t = threadIdx.x;
    int base = 0;
    for (int j = t; j < blockIdx.x; j += 256) base += g_bsum[j];
    red[t] = base; __syncthreads();
#pragma unroll
    for (int off = 128; off > 0; off >>= 1) {
        if (t < off) red[t] += red[t + off];
        __syncthreads();
    }
    int boff = red[0];
    int i = blockIdx.x * 256 + t;
    if (i < N_NODES) {
        int o = g_off[i] + boff;
        g_off[i] = o;
        g_cur[i] = o;
    }
}

// ---------------- place edges into CSR buckets (2 edges/thread, vectorized) ----------------
__global__ void k_place(const int* __restrict__ ei32) {
    int t = blockIdx.x * blockDim.x + threadIdx.x;   // 0 .. N_EDGES/2-1
    if (t >= N_EDGES / 2) return;
    int r0, r1, c0, c1;
    if (g_orflag == 0) {
        int4 vr = __ldg(&((const int4*)ei32)[t]);
        int4 vc = __ldg(&((const int4*)(ei32 + 2 * N_EDGES))[t]);
        r0 = vr.x; r1 = vr.z;
        c0 = vc.x; c1 = vc.z;
    } else {
        int2 vr = __ldg(&((const int2*)ei32)[t]);
        int2 vc = __ldg(&((const int2*)(ei32 + N_EDGES))[t]);
        r0 = vr.x; r1 = vr.y;
        c0 = vc.x; c1 = vc.y;
    }
    int p0 = atomicAdd(&g_cur[c0], 1);
    int p1 = atomicAdd(&g_cur[c1], 1);
    g_erow[p0] = r0;
    g_erow[p1] = r1;
}

// ---------------- tf32 tensor-core GEMM: g_xw = fp16(x @ W) ----------------
__global__ __launch_bounds__(256) void k_gemm(const float* __restrict__ x,
                                              const float* __restrict__ W) {
    __shared__ unsigned As[128][36];
    __shared__ unsigned Bs[32][136];
    const int m0   = blockIdx.x * 128;
    const int tid  = threadIdx.x;
    const int warp = tid >> 5;
    const int lane = tid & 31;
    const int wm   = warp >> 1;
    const int wn   = warp & 1;
    const int qr   = lane >> 2;
    const int qc   = lane & 3;

    float acc[2][8][4];
#pragma unroll
    for (int mi = 0; mi < 2; mi++)
#pragma unroll
        for (int ni = 0; ni < 8; ni++)
#pragma unroll
            for (int j = 0; j < 4; j++) acc[mi][ni][j] = 0.f;

#pragma unroll 1
    for (int kt = 0; kt < 4; kt++) {
#pragma unroll
        for (int i = 0; i < 16; i++) {
            int idx = tid + i * 256;
            int r = idx >> 5, c = idx & 31;
            int gr = m0 + r;
            float v = (gr < N_NODES) ? __ldg(&x[(size_t)gr * DIM + kt * 32 + c]) : 0.f;
            unsigned u;
            asm("cvt.rna.tf32.f32 %0, %1;" : "=r"(u) : "f"(v));
            As[r][c] = u;
        }
#pragma unroll
        for (int i = 0; i < 16; i++) {
            int idx = tid + i * 256;
            int r = idx >> 7, c = idx & 127;
            float v = __ldg(&W[(kt * 32 + r) * DIM + c]);
            unsigned u;
            asm("cvt.rna.tf32.f32 %0, %1;" : "=r"(u) : "f"(v));
            Bs[r][c] = u;
        }
        __syncthreads();

#pragma unroll
        for (int ks = 0; ks < 4; ks++) {
            const int k0 = ks * 8;
            unsigned a[2][4], bf[8][2];
#pragma unroll
            for (int mi = 0; mi < 2; mi++) {
                int rb = wm * 32 + mi * 16;
                a[mi][0] = As[rb + qr][k0 + qc];
                a[mi][1] = As[rb + qr + 8][k0 + qc];
                a[mi][2] = As[rb + qr][k0 + qc + 4];
                a[mi][3] = As[rb + qr + 8][k0 + qc + 4];
            }
#pragma unroll
            for (int ni = 0; ni < 8; ni++) {
                int cb = wn * 64 + ni * 8;
                bf[ni][0] = Bs[k0 + qc][cb + qr];
                bf[ni][1] = Bs[k0 + qc + 4][cb + qr];
            }
#pragma unroll
            for (int mi = 0; mi < 2; mi++)
#pragma unroll
                for (int ni = 0; ni < 8; ni++) {
                    asm volatile(
                        "mma.sync.aligned.m16n8k8.row.col.f32.tf32.tf32.f32 "
                        "{%0,%1,%2,%3}, {%4,%5,%6,%7}, {%8,%9}, {%0,%1,%2,%3};"
                        : "+f"(acc[mi][ni][0]), "+f"(acc[mi][ni][1]),
                          "+f"(acc[mi][ni][2]), "+f"(acc[mi][ni][3])
                        : "r"(a[mi][0]), "r"(a[mi][1]), "r"(a[mi][2]), "r"(a[mi][3]),
                          "r"(bf[ni][0]), "r"(bf[ni][1]));
                }
        }
        __syncthreads();
    }

#pragma unroll
    for (int mi = 0; mi < 2; mi++) {
        int r0 = m0 + wm * 32 + mi * 16 + qr;
        int r1 = r0 + 8;
#pragma unroll
        for (int ni = 0; ni < 8; ni++) {
            int cb = wn * 64 + ni * 8 + qc * 2;
            if (r0 < N_NODES)
                *(__half2*)&g_xw[(size_t)r0 * DIM + cb] =
                    __floats2half2_rn(acc[mi][ni][0], acc[mi][ni][1]);
            if (r1 < N_NODES)
                *(__half2*)&g_xw[(size_t)r1 * DIM + cb] =
                    __floats2half2_rn(acc[mi][ni][2], acc[mi][ni][3]);
        }
    }
}

// ---------------- CSR gather: warp/node, 2 edges per warp-instruction ----------------
// Row = 128 fp16 = 256 B = 16 lanes x uint4. Lanes 0-15 = edge e, lanes 16-31 = edge e+1.
__device__ __forceinline__ void hacc(float* a, const uint4& u, float w) {
    float2 f0 = __half22float2(*(const __half2*)&u.x);
    float2 f1 = __half22float2(*(const __half2*)&u.y);
    float2 f2 = __half22float2(*(const __half2*)&u.z);
    float2 f3 = __half22float2(*(const __half2*)&u.w);
    a[0] += f0.x * w; a[1] += f0.y * w;
    a[2] += f1.x * w; a[3] += f1.y * w;
    a[4] += f2.x * w; a[5] += f2.y * w;
    a[6] += f3.x * w; a[7] += f3.y * w;
}

__global__ __launch_bounds__(256) void k_gather(const float* __restrict__ b,
                                                float* __restrict__ out) {
    int n    = (blockIdx.x * blockDim.x + threadIdx.x) >> 5;
    int lane = threadIdx.x & 31;
    if (n >= N_NODES) return;
    int half = lane >> 4;      // 0 or 1
    int l16  = lane & 15;

    const uint4* xw4 = (const uint4*)g_xw;   // row stride = 16 uint4
    float dn = g_dis[n];

    float a[8];
#pragma unroll
    for (int i = 0; i < 8; i++) a[i] = 0.f;

    // self-loop: half 0 carries weight dn*dn, half 1 contributes 0
    {
        uint4 u = __ldg(&xw4[(size_t)n * 16 + l16]);
        hacc(a, u, (half == 0) ? dn * dn : 0.f);
    }

    int beg = g_off[n];
    int end = (n + 1 < N_NODES) ? g_off[n + 1] : N_EDGES;

    int e = beg;
    // unrolled: 4 edges per warp-iteration (2 per half-warp)
    for (; e + 3 < end; e += 4) {
        int r0 = __ldg(&g_erow[e + half]);
        int r1 = __ldg(&g_erow[e + 2 + half]);
        float w0 = __ldg(&g_dis[r0]) * dn;
        float w1 = __ldg(&g_dis[r1]) * dn;
        uint4 u0 = __ldg(&xw4[(size_t)r0 * 16 + l16]);
        uint4 u1 = __ldg(&xw4[(size_t)r1 * 16 + l16]);
        hacc(a, u0, w0);
        hacc(a, u1, w1);
    }
    // tail: predicated 2 edges per iteration
    for (; e < end; e += 2) {
        int idx = e + half;
        bool valid = idx < end;
        int r0 = valid ? __ldg(&g_erow[idx]) : n;
        float w0 = valid ? __ldg(&g_dis[r0]) * dn : 0.f;
        uint4 u0 = __ldg(&xw4[(size_t)r0 * 16 + l16]);
        hacc(a, u0, w0);
    }

    // combine halves
#pragma unroll
    for (int i = 0; i < 8; i++)
        a[i] += __shfl_xor_sync(0xffffffffu, a[i], 16);

    if (half == 0) {
        float4 b0 = ((const float4*)b)[l16 * 2];
        float4 b1 = ((const float4*)b)[l16 * 2 + 1];
        float4 o0 = make_float4(fmaxf(a[0] + b0.x, 0.f), fmaxf(a[1] + b0.y, 0.f),
                                fmaxf(a[2] + b0.z, 0.f), fmaxf(a[3] + b0.w, 0.f));
        float4 o1 = make_float4(fmaxf(a[4] + b1.x, 0.f), fmaxf(a[5] + b1.y, 0.f),
                                fmaxf(a[6] + b1.z, 0.f), fmaxf(a[7] + b1.w, 0.f));
        ((float4*)out)[(size_t)n * 32 + l16 * 2]     = o0;
        ((float4*)out)[(size_t)n * 32 + l16 * 2 + 1] = o1;
    }
}

extern "C" void kernel_launch(void* const* d_in, const int* in_sizes, int n_in,
                              void* d_out, int out_size) {
    // Identify inputs by element count:
    //   x: 12,800,000   edge_index: 3,200,000   W: 16,384   b: 128
    const float* x  = nullptr;
    const void*  ei = nullptr;
    const float* W  = nullptr;
    const float* b  = nullptr;
    for (int i = 0; i < n_in; i++) {
        switch (in_sizes[i]) {
            case 12800000: x  = (const float*)d_in[i]; break;
            case 3200000:  ei = d_in[i];               break;
            case 16384:    W  = (const float*)d_in[i]; break;
            case 128:      b  = (const float*)d_in[i]; break;
            default: break;
        }
    }
    float* out = (float*)d_out;
    const int* ei32 = (const int*)ei;

    // Fork: GEMM (depends only on x, W) runs on a side stream in parallel
    // with the edge-preprocessing chain; join before gather.
    cudaStream_t s2;
    cudaStreamCreateWithFlags(&s2, cudaStreamNonBlocking);
    cudaEvent_t ev_fork, ev_join;
    cudaEventCreateWithFlags(&ev_fork, cudaEventDisableTiming);
    cudaEventCreateWithFlags(&ev_join, cudaEventDisableTiming);

    cudaEventRecord(ev_fork, 0);
    cudaStreamWaitEvent(s2, ev_fork, 0);
    k_gemm<<<(N_NODES + 127) / 128, 256, 0, s2>>>(x, W);
    cudaEventRecord(ev_join, s2);

    // main-stream preprocessing chain
    k_init_detect<<<(N_NODES + 255) / 256, 256>>>(ei32);
    k_hist<<<(N_EDGES / 2 + 255) / 256, 256>>>(ei32);
    k_scan1<<<NB_SCAN, 256>>>();
    k_scan23<<<NB_SCAN, 256>>>();
    k_place<<<(N_EDGES / 2 + 255) / 256, 256>>>(ei32);

    cudaStreamWaitEvent(0, ev_join, 0);
    {
        long long total_threads = (long long)N_NODES * 32;
        int blocks = (int)((total_threads + 255) / 256);
        k_gather<<<blocks, 256>>>(b, out);
    }
}